// round 6
// baseline (speedup 1.0000x reference)
#include <cuda_runtime.h>
#include <cuda_bf16.h>

#define BB 64
#define TT 288
#define VV 24
#define DD 256
// TOD 128 | DOW 32 | DOM 32 | DOY 64

struct __align__(32) float8 { float4 a, b; };

__device__ __forceinline__ float8 ldg256_nc(const float8* p) {
    float8 r;
    asm volatile("ld.global.nc.v8.f32 {%0,%1,%2,%3,%4,%5,%6,%7}, [%8];"
        : "=f"(r.a.x), "=f"(r.a.y), "=f"(r.a.z), "=f"(r.a.w),
          "=f"(r.b.x), "=f"(r.b.y), "=f"(r.b.z), "=f"(r.b.w)
        : "l"(p));
    return r;
}

__device__ __forceinline__ void stg256_cs(float8* p, const float8& v) {
    asm volatile("st.global.cs.v8.f32 [%0], {%1,%2,%3,%4,%5,%6,%7,%8};"
        :: "l"(p),
           "f"(v.a.x), "f"(v.a.y), "f"(v.a.z), "f"(v.a.w),
           "f"(v.b.x), "f"(v.b.y), "f"(v.b.z), "f"(v.b.w)
        : "memory");
}

__global__ __launch_bounds__(256, 8) void input_embedding_kernel(
    const float* __restrict__ features,     // (B,T,V)
    const int*   __restrict__ bar_in_day,   // (B,T)
    const int*   __restrict__ day_of_week,  // (B,)
    const int*   __restrict__ day_of_month, // (B,)
    const int*   __restrict__ day_of_year,  // (B,)
    const float8* __restrict__ W,           // (V,D) as float8
    const float8* __restrict__ bias,        // (V,D) as float8
    const float* __restrict__ tod_table,    // (288,128)
    const float* __restrict__ dow_table,    // (7,32)
    const float* __restrict__ dom_table,    // (32,32)
    const float* __restrict__ doy_table,    // (367,64)
    float8* __restrict__ out)               // (B,T,V,D) as float8
{
    __shared__ __align__(32) float pos[DD];
    __shared__ float sx[VV];

    const int bt  = blockIdx.x;       // b*T + t
    const int b   = bt / TT;
    const int tid = threadIdx.x;

    // ---- build composite positional vector pos[0..255] in smem ----
    if (tid < 128) {
        const int tod = bar_in_day[bt];
        pos[tid] = tod_table[tod * 128 + tid];
    } else if (tid < 160) {
        pos[tid] = dow_table[day_of_week[b] * 32 + (tid - 128)];
    } else if (tid < 192) {
        pos[tid] = dom_table[day_of_month[b] * 32 + (tid - 160)];
    } else {
        pos[tid] = doy_table[day_of_year[b] * 64 + (tid - 192)];
    }
    if (tid < VV) sx[tid] = features[bt * VV + tid];
    __syncthreads();

    const float4* __restrict__ pos4 = reinterpret_cast<const float4*>(pos);
    float8* __restrict__ outb = out + (size_t)bt * (VV * DD / 8);

    // 24 rows of 32 float8 = 768 float8 per block; 3 per thread.
    #pragma unroll
    for (int k = 0; k < 3; k++) {
        const int p  = tid + k * 256;   // 0..767
        const int v  = p >> 5;          // uniform across each warp
        const int d8 = p & 31;
        const float  x  = sx[v];
        const float8 w  = ldg256_nc(&W[v * 32 + d8]);
        const float8 bv = ldg256_nc(&bias[v * 32 + d8]);
        const float4 p0 = pos4[d8 * 2];
        const float4 p1 = pos4[d8 * 2 + 1];
        float8 o;
        o.a.x = fmaf(x, w.a.x, bv.a.x) + p0.x;
        o.a.y = fmaf(x, w.a.y, bv.a.y) + p0.y;
        o.a.z = fmaf(x, w.a.z, bv.a.z) + p0.z;
        o.a.w = fmaf(x, w.a.w, bv.a.w) + p0.w;
        o.b.x = fmaf(x, w.b.x, bv.b.x) + p1.x;
        o.b.y = fmaf(x, w.b.y, bv.b.y) + p1.y;
        o.b.z = fmaf(x, w.b.z, bv.b.z) + p1.z;
        o.b.w = fmaf(x, w.b.w, bv.b.w) + p1.w;
        stg256_cs(&outb[p], o);         // 256-bit streaming store
    }
}

extern "C" void kernel_launch(void* const* d_in, const int* in_sizes, int n_in,
                              void* d_out, int out_size) {
    const float* features     = (const float*)d_in[0];
    const int*   bar_in_day   = (const int*)d_in[1];
    const int*   day_of_week  = (const int*)d_in[2];
    const int*   day_of_month = (const int*)d_in[3];
    const int*   day_of_year  = (const int*)d_in[4];
    const float8* W           = (const float8*)d_in[5];
    const float8* bias        = (const float8*)d_in[6];
    const float* tod_table    = (const float*)d_in[7];
    const float* dow_table    = (const float*)d_in[8];
    const float* dom_table    = (const float*)d_in[9];
    const float* doy_table    = (const float*)d_in[10];
    float8* out = (float8*)d_out;

    input_embedding_kernel<<<BB * TT, 256>>>(
        features, bar_in_day, day_of_week, day_of_month, day_of_year,
        W, bias, tod_table, dow_table, dom_table, doy_table, out);
}

// round 7
// speedup vs baseline: 1.0910x; 1.0910x over previous
#include <cuda_runtime.h>
#include <cuda_bf16.h>

#define BB 64
#define TT 288
#define VV 24
#define DD 256
// TOD 128 | DOW 32 | DOM 32 | DOY 64

__global__ __launch_bounds__(128, 16) void input_embedding_kernel(
    const float* __restrict__ features,     // (B,T,V)
    const int*   __restrict__ bar_in_day,   // (B,T)
    const int*   __restrict__ day_of_week,  // (B,)
    const int*   __restrict__ day_of_month, // (B,)
    const int*   __restrict__ day_of_year,  // (B,)
    const float4* __restrict__ W,           // (V,D) as float4
    const float4* __restrict__ bias,        // (V,D) as float4
    const float* __restrict__ tod_table,    // (288,128)
    const float* __restrict__ dow_table,    // (7,32)
    const float* __restrict__ dom_table,    // (32,32)
    const float* __restrict__ doy_table,    // (367,64)
    float4* __restrict__ out)               // (B,T,V,D) as float4
{
    __shared__ __align__(16) float pos[DD];
    __shared__ float sx[VV];

    const int bt  = blockIdx.x;       // b*T + t
    const int b   = bt / TT;
    const int tid = threadIdx.x;      // 0..127

    // ---- build composite positional vector pos[0..255] in smem ----
    // first half: tod[0..127]; second half handled by tid+128 mapping below
    {
        pos[tid] = tod_table[bar_in_day[bt] * 128 + tid];   // all 128 threads: tod
        const int t2 = tid + 128;                            // 128..255
        float v2;
        if (t2 < 160)      v2 = dow_table[day_of_week[b] * 32 + (t2 - 128)];
        else if (t2 < 192) v2 = dom_table[day_of_month[b] * 32 + (t2 - 160)];
        else               v2 = doy_table[day_of_year[b] * 64 + (t2 - 192)];
        pos[t2] = v2;
    }
    if (tid < VV) sx[tid] = features[bt * VV + tid];
    __syncthreads();

    const float4* __restrict__ pos4 = reinterpret_cast<const float4*>(pos);
    float4* __restrict__ outb = out + (size_t)bt * (VV * DD / 4);

    // 24 rows of 64 float4 = 1536 float4 per block; 12 per thread.
    #pragma unroll
    for (int k = 0; k < 12; k++) {
        const int p  = tid + k * 128;   // 0..1535
        const int v  = p >> 6;          // uniform across each warp
        const int d4 = p & 63;
        const float  x  = sx[v];
        const float4 w  = W[v * 64 + d4];
        const float4 bv = bias[v * 64 + d4];
        const float4 pp = pos4[d4];
        float4 o;
        o.x = fmaf(x, w.x, bv.x) + pp.x;
        o.y = fmaf(x, w.y, bv.y) + pp.y;
        o.z = fmaf(x, w.z, bv.z) + pp.z;
        o.w = fmaf(x, w.w, bv.w) + pp.w;
        __stcs(&outb[p], o);            // streaming store: keep output out of L2
    }
}

extern "C" void kernel_launch(void* const* d_in, const int* in_sizes, int n_in,
                              void* d_out, int out_size) {
    const float* features     = (const float*)d_in[0];
    const int*   bar_in_day   = (const int*)d_in[1];
    const int*   day_of_week  = (const int*)d_in[2];
    const int*   day_of_month = (const int*)d_in[3];
    const int*   day_of_year  = (const int*)d_in[4];
    const float4* W           = (const float4*)d_in[5];
    const float4* bias        = (const float4*)d_in[6];
    const float* tod_table    = (const float*)d_in[7];
    const float* dow_table    = (const float*)d_in[8];
    const float* dom_table    = (const float*)d_in[9];
    const float* doy_table    = (const float*)d_in[10];
    float4* out = (float4*)d_out;

    input_embedding_kernel<<<BB * TT, 128>>>(
        features, bar_in_day, day_of_week, day_of_month, day_of_year,
        W, bias, tod_table, dow_table, dom_table, doy_table, out);
}